// round 15
// baseline (speedup 1.0000x reference)
#include <cuda_runtime.h>
#include <cuda_bf16.h>
#include <math.h>
#include <stdint.h>

#define NROWS 8192
#define DDIM  256
#define TWO_N 16384
// A(64KB) + B0(64KB) + B1(64KB)
#define SMEM_BYTES (3 * 65536)

// scratch: normalized z rows (bf16), [z1hat; z2hat] = [16384, 256]
__device__ __nv_bfloat16 g_Zn[(size_t)TWO_N * DDIM];
// per-row sum of exp(sim-10), masked diag
__device__ float g_rsum[TWO_N];
// accumulators: 0=price 1=change 2=crit 3=posdot 4=lse_sum
__device__ float g_acc[8];
__device__ int g_done;

// ---------------------------------------------------------------------------
__global__ void init_kernel() {
    int i = blockIdx.x * blockDim.x + threadIdx.x;
    if (i < TWO_N) g_rsum[i] = 0.f;
    if (i < 8) g_acc[i] = 0.f;
    if (i == 8) g_done = 0;
}

// ---------------------------------------------------------------------------
// Fused: normalize z1/z2 rows -> bf16 g_Zn + positive-pair dots (all blocks),
// plus supervised losses (blocks 0..31).
__global__ void prep_kernel(const float* __restrict__ z1, const float* __restrict__ z2,
                            const float* __restrict__ pp, const float* __restrict__ pt,
                            const float* __restrict__ cp, const float* __restrict__ ct,
                            const float* __restrict__ xp, const float* __restrict__ xt) {
    // ---- supervised part: blocks 0..31 cover 8192 elements exactly once
    if (blockIdx.x < 32) {
        int i = blockIdx.x * blockDim.x + threadIdx.x;
        float d = pp[i] - pt[i]; float s0 = d * d;
        d = cp[i] - ct[i];       float s1 = d * d;
        float x = xp[i], t = xt[i];
        float s2 = fmaxf(x, 0.f) - x * t + log1pf(expf(-fabsf(x)));
        #pragma unroll
        for (int o = 16; o; o >>= 1) {
            s0 += __shfl_xor_sync(0xffffffffu, s0, o);
            s1 += __shfl_xor_sync(0xffffffffu, s1, o);
            s2 += __shfl_xor_sync(0xffffffffu, s2, o);
        }
        if ((threadIdx.x & 31) == 0) {
            atomicAdd(&g_acc[0], s0);
            atomicAdd(&g_acc[1], s1);
            atomicAdd(&g_acc[2], s2);
        }
    }

    // ---- normalization part: one warp per row
    int warp = (blockIdx.x * blockDim.x + threadIdx.x) >> 5;
    int lane = threadIdx.x & 31;
    if (warp >= NROWS) return;

    const float4* r1 = (const float4*)(z1 + (size_t)warp * DDIM);
    const float4* r2 = (const float4*)(z2 + (size_t)warp * DDIM);
    float4 a0 = r1[lane * 2], a1 = r1[lane * 2 + 1];
    float4 b0 = r2[lane * 2], b1 = r2[lane * 2 + 1];

    float s11 = a0.x*a0.x + a0.y*a0.y + a0.z*a0.z + a0.w*a0.w
              + a1.x*a1.x + a1.y*a1.y + a1.z*a1.z + a1.w*a1.w;
    float s22 = b0.x*b0.x + b0.y*b0.y + b0.z*b0.z + b0.w*b0.w
              + b1.x*b1.x + b1.y*b1.y + b1.z*b1.z + b1.w*b1.w;
    float s12 = a0.x*b0.x + a0.y*b0.y + a0.z*b0.z + a0.w*b0.w
              + a1.x*b1.x + a1.y*b1.y + a1.z*b1.z + a1.w*b1.w;
    #pragma unroll
    for (int o = 16; o; o >>= 1) {
        s11 += __shfl_xor_sync(0xffffffffu, s11, o);
        s22 += __shfl_xor_sync(0xffffffffu, s22, o);
        s12 += __shfl_xor_sync(0xffffffffu, s12, o);
    }
    float n1 = fmaxf(sqrtf(s11), 1e-12f);
    float n2 = fmaxf(sqrtf(s22), 1e-12f);
    float i1 = 1.f / n1, i2 = 1.f / n2;

    __nv_bfloat162* o1 = (__nv_bfloat162*)(g_Zn + (size_t)warp * DDIM + lane * 8);
    __nv_bfloat162* o2 = (__nv_bfloat162*)(g_Zn + (size_t)(warp + NROWS) * DDIM + lane * 8);
    o1[0] = __floats2bfloat162_rn(a0.x * i1, a0.y * i1);
    o1[1] = __floats2bfloat162_rn(a0.z * i1, a0.w * i1);
    o1[2] = __floats2bfloat162_rn(a1.x * i1, a1.y * i1);
    o1[3] = __floats2bfloat162_rn(a1.z * i1, a1.w * i1);
    o2[0] = __floats2bfloat162_rn(b0.x * i2, b0.y * i2);
    o2[1] = __floats2bfloat162_rn(b0.z * i2, b0.w * i2);
    o2[2] = __floats2bfloat162_rn(b1.x * i2, b1.y * i2);
    o2[3] = __floats2bfloat162_rn(b1.z * i2, b1.w * i2);

    if (lane == 0) atomicAdd(&g_acc[3], s12 * i1 * i2);
}

// ---------------------------------------------------------------------------
// GEMM + exp + symmetric row/col accumulation.
__device__ __forceinline__ uint32_t sw_off(int r, int ch) {
    return (uint32_t)(r * 512 + ((ch ^ (r & 7)) << 4));
}

__device__ __forceinline__ void ldsm4(uint32_t* r, uint32_t addr) {
    asm("ldmatrix.sync.aligned.m8n8.x4.shared.b16 {%0,%1,%2,%3}, [%4];"
        : "=r"(r[0]), "=r"(r[1]), "=r"(r[2]), "=r"(r[3]) : "r"(addr) : "memory");
}

__device__ __forceinline__ void mma16816(float* c, const uint32_t* a, const uint32_t* b) {
    asm("mma.sync.aligned.m16n8k16.row.col.f32.bf16.bf16.f32 "
        "{%0,%1,%2,%3}, {%4,%5,%6,%7}, {%8,%9}, {%0,%1,%2,%3};"
        : "+f"(c[0]), "+f"(c[1]), "+f"(c[2]), "+f"(c[3])
        : "r"(a[0]), "r"(a[1]), "r"(a[2]), "r"(a[3]), "r"(b[0]), "r"(b[1]));
}

__device__ __forceinline__ void cp16(uint32_t dst, const void* src) {
    asm volatile("cp.async.cg.shared.global [%0], [%1], 16;"
                 :: "r"(dst), "l"(src));
}
__device__ __forceinline__ void cp_commit() {
    asm volatile("cp.async.commit_group;");
}
template <int N>
__device__ __forceinline__ void cp_wait() {
    asm volatile("cp.async.wait_group %0;" :: "n"(N) : "memory");
}

// exp(10*v - 10) = exp2(v*K - K), K = 10*log2(e); single MUFU EX2
__device__ __forceinline__ float ex2(float x) {
    float r;
    asm("ex2.approx.f32 %0, %1;" : "=f"(r) : "f"(x));
    return r;
}
#define EXPK 14.4269504088896f

// 4 warps (128 thr), 2x2 warp grid, each warp computes 64x64 of the 128x128
// tile. Fragment smem traffic drops 384KB -> 256KB per tile vs the 4x2 grid.
__global__ void __launch_bounds__(128, 1) ntxent_kernel() {
    extern __shared__ char smem[];
    const int tid  = threadIdx.x;
    const int lane = tid & 31;
    const int wid  = tid >> 5;
    const int warpM = wid >> 1;  // 0..1 (64 rows each)
    const int warpN = wid & 1;   // 0..1 (64 cols each)
    const int br = blockIdx.x;   // 0..127 row block
    // wrap mapping: CTA br computes tiles j = br..br+63 (mod 128),
    // plus antipodal j=br+64 when br<64. Each unordered pair once.
    const int ntiles = (br < 64) ? 65 : 64;

    const uint4* gz = (const uint4*)g_Zn;  // 32 uint4 per 256-bf16 row

    uint32_t sbase = (uint32_t)__cvta_generic_to_shared(smem);
    const uint32_t sA = sbase;
    const uint32_t sB[2] = {sbase + 65536, sbase + 2 * 65536};

    // prologue: A tile (rows br*128..) + B tile jj=0 (4096 chunks / 128 thr)
    #pragma unroll
    for (int it = 0; it < 32; it++) {
        int idx = tid + it * 128;
        int r = idx >> 5, ch = idx & 31;
        uint32_t off = sw_off(r, ch);
        cp16(sA + off, gz + (size_t)(br * 128 + r) * 32 + ch);
        cp16(sB[0] + off, gz + (size_t)(br * 128 + r) * 32 + ch);
    }
    cp_commit();

    const int g = lane >> 2, q = lane & 3;
    float racc[8];
    #pragma unroll
    for (int k = 0; k < 8; k++) racc[k] = 0.f;

    const int ar_base = warpM * 64 + (lane & 15);
    const int a_chadd = lane >> 4;
    const int bn_thr  = warpN * 64 + ((lane >> 4) << 3) + (lane & 7);
    const int b_chadd = (lane >> 3) & 1;

    for (int jj = 0; jj < ntiles; jj++) {
        const int j = (br + jj) & 127;
        const int cur = jj & 1;

        cp_wait<0>();      // drain the single pending group (tile jj's data)
        __syncthreads();   // all warps: tile jj visible AND tile jj-1 consumed

        // prefetch tile jj+1 into the other buffer (safe: post-barrier, the
        // buffer's last readers finished tile jj-1 before arriving here)
        if (jj + 1 < ntiles) {
            const int nxt = cur ^ 1;
            const int j2 = (br + jj + 1) & 127;
            #pragma unroll
            for (int it = 0; it < 32; it++) {
                int idx = tid + it * 128;
                int r = idx >> 5, ch = idx & 31;
                cp16(sB[nxt] + sw_off(r, ch),
                     gz + (size_t)(j2 * 128 + r) * 32 + ch);
            }
            cp_commit();
        }

        float c[4][8][4];
        #pragma unroll
        for (int mt = 0; mt < 4; mt++)
            #pragma unroll
            for (int nt = 0; nt < 8; nt++)
                #pragma unroll
                for (int e = 0; e < 4; e++) c[mt][nt][e] = 0.f;

        #pragma unroll
        for (int ks = 0; ks < 16; ks++) {
            uint32_t a[4][4];
            #pragma unroll
            for (int mt = 0; mt < 4; mt++) {
                int r  = ar_base + mt * 16;
                int ch = ks * 2 + a_chadd;
                ldsm4(a[mt], sA + sw_off(r, ch));
            }
            uint32_t b[8][2];
            #pragma unroll
            for (int p = 0; p < 4; p++) {
                int n  = bn_thr + p * 16;
                int ch = ks * 2 + b_chadd;
                uint32_t t[4];
                ldsm4(t, sB[cur] + sw_off(n, ch));
                b[2 * p][0] = t[0]; b[2 * p][1] = t[1];
                b[2 * p + 1][0] = t[2]; b[2 * p + 1][1] = t[3];
            }
            #pragma unroll
            for (int mt = 0; mt < 4; mt++)
                #pragma unroll
                for (int nt = 0; nt < 8; nt++)
                    mma16816(c[mt][nt], a[mt], b[nt]);
        }

        // epilogue: exp(10*sim - 10); row-side into racc, col-side (transpose,
        // feeds row sums of block j) via shfl-reduce + global float atomics.
        const bool diag = (jj == 0);
        #pragma unroll
        for (int nt = 0; nt < 8; nt++) {
            float cs0 = 0.f, cs1 = 0.f;
            #pragma unroll
            for (int mt = 0; mt < 4; mt++) {
                #pragma unroll
                for (int h = 0; h < 2; h++) {
                    float e0 = ex2(fmaf(c[mt][nt][h * 2 + 0], EXPK, -EXPK));
                    float e1 = ex2(fmaf(c[mt][nt][h * 2 + 1], EXPK, -EXPK));
                    if (diag) {
                        int rl = warpM * 64 + mt * 16 + h * 8 + g;
                        int cb = warpN * 64 + nt * 8 + 2 * q;
                        if (rl == cb)     e0 = 0.f;
                        if (rl == cb + 1) e1 = 0.f;
                    }
                    racc[mt * 2 + h] += e0 + e1;
                    cs0 += e0; cs1 += e1;
                }
            }
            if (!diag) {
                #pragma unroll
                for (int o = 4; o <= 16; o <<= 1) {
                    cs0 += __shfl_xor_sync(0xffffffffu, cs0, o);
                    cs1 += __shfl_xor_sync(0xffffffffu, cs1, o);
                }
                if (lane < 4) {
                    int col = warpN * 64 + nt * 8 + 2 * lane;
                    atomicAdd(&g_rsum[j * 128 + col],     cs0);
                    atomicAdd(&g_rsum[j * 128 + col + 1], cs1);
                }
            }
        }
    }

    // row-side: reduce racc across quad lanes, one atomic per row per warp
    #pragma unroll
    for (int k = 0; k < 8; k++) {
        float v = racc[k];
        v += __shfl_xor_sync(0xffffffffu, v, 1);
        v += __shfl_xor_sync(0xffffffffu, v, 2);
        if (q == 0) {
            int r = warpM * 64 + (k >> 1) * 16 + (k & 1) * 8 + g;
            atomicAdd(&g_rsum[br * 128 + r], v);
        }
    }
}

// ---------------------------------------------------------------------------
// Fused lse + finish: 64 blocks reduce lse; the last block writes the output.
__global__ void lse_kernel(float* __restrict__ out) {
    int i = blockIdx.x * blockDim.x + threadIdx.x;
    float lse = 10.f + __logf(g_rsum[i]);
    #pragma unroll
    for (int o = 16; o; o >>= 1) lse += __shfl_xor_sync(0xffffffffu, lse, o);
    __shared__ float sh[8];
    __shared__ bool last;
    int lane = threadIdx.x & 31, w = threadIdx.x >> 5;
    if (lane == 0) sh[w] = lse;
    __syncthreads();
    if (threadIdx.x == 0) {
        float t = 0.f;
        for (int k = 0; k < 8; k++) t += sh[k];
        atomicAdd(&g_acc[4], t);
        __threadfence();
        last = (atomicAdd(&g_done, 1) == 63);
    }
    __syncthreads();
    if (last && threadIdx.x == 0) {
        const float inv = 1.f / 8192.f;
        float sup = g_acc[0] * inv + 0.5f * g_acc[1] * inv + 0.3f * g_acc[2] * inv;
        // sum_i sim_pos = 2 * posdotsum / 0.1 = 20 * posdotsum
        float ssl = (g_acc[4] - 20.f * g_acc[3]) * (1.f / 16384.f);
        out[0] = sup + 0.1f * ssl;
    }
}

// ---------------------------------------------------------------------------
extern "C" void kernel_launch(void* const* d_in, const int* in_sizes, int n_in,
                              void* d_out, int out_size) {
    const float* pp = (const float*)d_in[0];
    const float* pt = (const float*)d_in[1];
    const float* cp = (const float*)d_in[2];
    const float* ct = (const float*)d_in[3];
    const float* xp = (const float*)d_in[4];
    const float* xt = (const float*)d_in[5];
    const float* z1 = (const float*)d_in[6];
    const float* z2 = (const float*)d_in[7];
    float* out = (float*)d_out;

    cudaFuncSetAttribute(ntxent_kernel, cudaFuncAttributeMaxDynamicSharedMemorySize,
                         SMEM_BYTES);

    init_kernel<<<64, 256>>>();
    prep_kernel<<<NROWS / 8, 256>>>(z1, z2, pp, pt, cp, ct, xp, xt);
    ntxent_kernel<<<128, 128, SMEM_BYTES>>>();
    lse_kernel<<<64, 256>>>(out);
}

// round 17
// speedup vs baseline: 1.2780x; 1.2780x over previous
#include <cuda_runtime.h>
#include <cuda_bf16.h>
#include <math.h>
#include <stdint.h>

#define NROWS 8192
#define DDIM  256
#define TWO_N 16384
// A(64KB) + B0(64KB) + B1(64KB)
#define SMEM_BYTES (3 * 65536)

// scratch: normalized z rows (bf16), [z1hat; z2hat] = [16384, 256]
__device__ __nv_bfloat16 g_Zn[(size_t)TWO_N * DDIM];
// per-row sum of exp(sim-10), masked diag (zeroed by prep_kernel)
__device__ float g_rsum[TWO_N];
// partial sums (written unconditionally -> no pre-zero needed)
__device__ float g_sup0[32], g_sup1[32], g_sup2[32];  // supervised per-block
__device__ float g_pos[1024];                          // posdot per-block
__device__ float g_lse[64];                            // lse per-block
__device__ int g_done = 0;   // reset by lse's last block each launch

// ---------------------------------------------------------------------------
// Fused: zero g_rsum (blocks 0..63), supervised losses (blocks 0..31),
// normalize z1/z2 rows -> bf16 g_Zn + positive-pair dots (all 1024 blocks).
__global__ void prep_kernel(const float* __restrict__ z1, const float* __restrict__ z2,
                            const float* __restrict__ pp, const float* __restrict__ pt,
                            const float* __restrict__ cp, const float* __restrict__ ct,
                            const float* __restrict__ xp, const float* __restrict__ xt) {
    __shared__ float sh[4][8];
    const int tid = threadIdx.x;
    const int lane = tid & 31;
    const int wib = tid >> 5;   // warp in block, 0..7
    const int bid = blockIdx.x;

    // ---- zero g_rsum: blocks 0..63 cover 16384 floats
    if (bid < 64) g_rsum[bid * 256 + tid] = 0.f;

    // ---- supervised part: blocks 0..31 cover 8192 elements exactly once
    if (bid < 32) {
        int i = bid * 256 + tid;
        float d = pp[i] - pt[i]; float s0 = d * d;
        d = cp[i] - ct[i];       float s1 = d * d;
        float x = xp[i], t = xt[i];
        float s2 = fmaxf(x, 0.f) - x * t + log1pf(expf(-fabsf(x)));
        #pragma unroll
        for (int o = 16; o; o >>= 1) {
            s0 += __shfl_xor_sync(0xffffffffu, s0, o);
            s1 += __shfl_xor_sync(0xffffffffu, s1, o);
            s2 += __shfl_xor_sync(0xffffffffu, s2, o);
        }
        if (lane == 0) { sh[0][wib] = s0; sh[1][wib] = s1; sh[2][wib] = s2; }
    }

    // ---- normalization part: one warp per row (grid 1024x256 = 8192 warps)
    int row = bid * 8 + wib;

    const float4* r1 = (const float4*)(z1 + (size_t)row * DDIM);
    const float4* r2 = (const float4*)(z2 + (size_t)row * DDIM);
    float4 a0 = r1[lane * 2], a1 = r1[lane * 2 + 1];
    float4 b0 = r2[lane * 2], b1 = r2[lane * 2 + 1];

    float s11 = a0.x*a0.x + a0.y*a0.y + a0.z*a0.z + a0.w*a0.w
              + a1.x*a1.x + a1.y*a1.y + a1.z*a1.z + a1.w*a1.w;
    float s22 = b0.x*b0.x + b0.y*b0.y + b0.z*b0.z + b0.w*b0.w
              + b1.x*b1.x + b1.y*b1.y + b1.z*b1.z + b1.w*b1.w;
    float s12 = a0.x*b0.x + a0.y*b0.y + a0.z*b0.z + a0.w*b0.w
              + a1.x*b1.x + a1.y*b1.y + a1.z*b1.z + a1.w*b1.w;
    #pragma unroll
    for (int o = 16; o; o >>= 1) {
        s11 += __shfl_xor_sync(0xffffffffu, s11, o);
        s22 += __shfl_xor_sync(0xffffffffu, s22, o);
        s12 += __shfl_xor_sync(0xffffffffu, s12, o);
    }
    float n1 = fmaxf(sqrtf(s11), 1e-12f);
    float n2 = fmaxf(sqrtf(s22), 1e-12f);
    float i1 = 1.f / n1, i2 = 1.f / n2;

    __nv_bfloat162* o1 = (__nv_bfloat162*)(g_Zn + (size_t)row * DDIM + lane * 8);
    __nv_bfloat162* o2 = (__nv_bfloat162*)(g_Zn + (size_t)(row + NROWS) * DDIM + lane * 8);
    o1[0] = __floats2bfloat162_rn(a0.x * i1, a0.y * i1);
    o1[1] = __floats2bfloat162_rn(a0.z * i1, a0.w * i1);
    o1[2] = __floats2bfloat162_rn(a1.x * i1, a1.y * i1);
    o1[3] = __floats2bfloat162_rn(a1.z * i1, a1.w * i1);
    o2[0] = __floats2bfloat162_rn(b0.x * i2, b0.y * i2);
    o2[1] = __floats2bfloat162_rn(b0.z * i2, b0.w * i2);
    o2[2] = __floats2bfloat162_rn(b1.x * i2, b1.y * i2);
    o2[3] = __floats2bfloat162_rn(b1.z * i2, b1.w * i2);

    if (lane == 0) sh[3][wib] = s12 * i1 * i2;
    __syncthreads();
    if (tid == 0) {
        float p = 0.f;
        for (int k = 0; k < 8; k++) p += sh[3][k];
        g_pos[bid] = p;
        if (bid < 32) {
            float t0 = 0.f, t1 = 0.f, t2 = 0.f;
            for (int k = 0; k < 8; k++) { t0 += sh[0][k]; t1 += sh[1][k]; t2 += sh[2][k]; }
            g_sup0[bid] = t0; g_sup1[bid] = t1; g_sup2[bid] = t2;
        }
    }
}

// ---------------------------------------------------------------------------
// GEMM + exp + symmetric row/col accumulation.
__device__ __forceinline__ uint32_t sw_off(int r, int ch) {
    return (uint32_t)(r * 512 + ((ch ^ (r & 7)) << 4));
}

__device__ __forceinline__ void ldsm4(uint32_t* r, uint32_t addr) {
    asm("ldmatrix.sync.aligned.m8n8.x4.shared.b16 {%0,%1,%2,%3}, [%4];"
        : "=r"(r[0]), "=r"(r[1]), "=r"(r[2]), "=r"(r[3]) : "r"(addr) : "memory");
}

__device__ __forceinline__ void mma16816(float* c, const uint32_t* a, const uint32_t* b) {
    asm("mma.sync.aligned.m16n8k16.row.col.f32.bf16.bf16.f32 "
        "{%0,%1,%2,%3}, {%4,%5,%6,%7}, {%8,%9}, {%0,%1,%2,%3};"
        : "+f"(c[0]), "+f"(c[1]), "+f"(c[2]), "+f"(c[3])
        : "r"(a[0]), "r"(a[1]), "r"(a[2]), "r"(a[3]), "r"(b[0]), "r"(b[1]));
}

__device__ __forceinline__ void cp16(uint32_t dst, const void* src) {
    asm volatile("cp.async.cg.shared.global [%0], [%1], 16;"
                 :: "r"(dst), "l"(src));
}
__device__ __forceinline__ void cp_commit() {
    asm volatile("cp.async.commit_group;");
}
template <int N>
__device__ __forceinline__ void cp_wait() {
    asm volatile("cp.async.wait_group %0;" :: "n"(N) : "memory");
}

// exp(10*v - 10) = exp2(v*K - K), K = 10*log2(e); single MUFU EX2
__device__ __forceinline__ float ex2(float x) {
    float r;
    asm("ex2.approx.f32 %0, %1;" : "=f"(r) : "f"(x));
    return r;
}
#define EXPK 14.4269504088896f

__global__ void __launch_bounds__(256, 1) ntxent_kernel() {
    extern __shared__ char smem[];
    const int tid  = threadIdx.x;
    const int lane = tid & 31;
    const int wid  = tid >> 5;
    const int warpM = wid >> 1;  // 0..3 (rows)
    const int warpN = wid & 1;   // 0..1 (cols)
    const int br = blockIdx.x;   // 0..127 row block
    // wrap mapping: CTA br computes tiles j = br..br+63 (mod 128),
    // plus antipodal j=br+64 when br<64. Each unordered pair once.
    const int ntiles = (br < 64) ? 65 : 64;

    const uint4* gz = (const uint4*)g_Zn;  // 32 uint4 per 256-bf16 row

    uint32_t sbase = (uint32_t)__cvta_generic_to_shared(smem);
    const uint32_t sA = sbase;
    const uint32_t sB[2] = {sbase + 65536, sbase + 2 * 65536};

    // prologue: A tile (rows br*128..) + B tile jj=0 (j=br, the diag tile)
    #pragma unroll
    for (int it = 0; it < 16; it++) {
        int idx = tid + it * 256;
        int r = idx >> 5, ch = idx & 31;
        uint32_t off = sw_off(r, ch);
        cp16(sA + off, gz + (size_t)(br * 128 + r) * 32 + ch);
        cp16(sB[0] + off, gz + (size_t)(br * 128 + r) * 32 + ch);
    }
    cp_commit();

    const int g = lane >> 2, q = lane & 3;
    float racc[4] = {0.f, 0.f, 0.f, 0.f};

    const int ar_base = warpM * 32 + (lane & 15);
    const int a_chadd = lane >> 4;
    const int bn_thr  = warpN * 64 + ((lane >> 4) << 3) + (lane & 7);
    const int b_chadd = (lane >> 3) & 1;

    for (int jj = 0; jj < ntiles; jj++) {
        const int j = (br + jj) & 127;
        const int cur = jj & 1;

        cp_wait<0>();      // drain the single pending group (tile jj's data)
        __syncthreads();   // all warps: tile jj visible AND tile jj-1 consumed

        // prefetch tile jj+1 into the other buffer (safe: post-barrier, the
        // buffer's last readers finished tile jj-1 before arriving here)
        if (jj + 1 < ntiles) {
            const int nxt = cur ^ 1;
            const int j2 = (br + jj + 1) & 127;
            #pragma unroll
            for (int it = 0; it < 16; it++) {
                int idx = tid + it * 256;
                int r = idx >> 5, ch = idx & 31;
                cp16(sB[nxt] + sw_off(r, ch),
                     gz + (size_t)(j2 * 128 + r) * 32 + ch);
            }
            cp_commit();
        }

        float c[2][8][4];
        #pragma unroll
        for (int mt = 0; mt < 2; mt++)
            #pragma unroll
            for (int nt = 0; nt < 8; nt++)
                #pragma unroll
                for (int e = 0; e < 4; e++) c[mt][nt][e] = 0.f;

        #pragma unroll
        for (int ks = 0; ks < 16; ks++) {
            uint32_t a[2][4];
            #pragma unroll
            for (int mt = 0; mt < 2; mt++) {
                int r  = ar_base + mt * 16;
                int ch = ks * 2 + a_chadd;
                ldsm4(a[mt], sA + sw_off(r, ch));
            }
            uint32_t b[8][2];
            #pragma unroll
            for (int p = 0; p < 4; p++) {
                int n  = bn_thr + p * 16;
                int ch = ks * 2 + b_chadd;
                uint32_t t[4];
                ldsm4(t, sB[cur] + sw_off(n, ch));
                b[2 * p][0] = t[0]; b[2 * p][1] = t[1];
                b[2 * p + 1][0] = t[2]; b[2 * p + 1][1] = t[3];
            }
            #pragma unroll
            for (int mt = 0; mt < 2; mt++)
                #pragma unroll
                for (int nt = 0; nt < 8; nt++)
                    mma16816(c[mt][nt], a[mt], b[nt]);
        }

        // epilogue: exp(10*sim - 10); row-side into racc, col-side (transpose,
        // feeds row sums of block j) via shfl-reduce + global float atomics.
        const bool diag = (jj == 0);
        #pragma unroll
        for (int nt = 0; nt < 8; nt++) {
            float cs0 = 0.f, cs1 = 0.f;
            #pragma unroll
            for (int mt = 0; mt < 2; mt++) {
                #pragma unroll
                for (int h = 0; h < 2; h++) {
                    float e0 = ex2(fmaf(c[mt][nt][h * 2 + 0], EXPK, -EXPK));
                    float e1 = ex2(fmaf(c[mt][nt][h * 2 + 1], EXPK, -EXPK));
                    if (diag) {
                        int rl = warpM * 32 + mt * 16 + h * 8 + g;
                        int cb = warpN * 64 + nt * 8 + 2 * q;
                        if (rl == cb)     e0 = 0.f;
                        if (rl == cb + 1) e1 = 0.f;
                    }
                    racc[mt * 2 + h] += e0 + e1;
                    cs0 += e0; cs1 += e1;
                }
            }
            if (!diag) {
                #pragma unroll
                for (int o = 4; o <= 16; o <<= 1) {
                    cs0 += __shfl_xor_sync(0xffffffffu, cs0, o);
                    cs1 += __shfl_xor_sync(0xffffffffu, cs1, o);
                }
                if (lane < 4) {
                    int col = warpN * 64 + nt * 8 + 2 * lane;
                    atomicAdd(&g_rsum[j * 128 + col],     cs0);
                    atomicAdd(&g_rsum[j * 128 + col + 1], cs1);
                }
            }
        }
    }

    // row-side: reduce racc across quad lanes, one atomic per row per warp
    #pragma unroll
    for (int k = 0; k < 4; k++) {
        float v = racc[k];
        v += __shfl_xor_sync(0xffffffffu, v, 1);
        v += __shfl_xor_sync(0xffffffffu, v, 2);
        if (q == 0) {
            int r = warpM * 32 + (k >> 1) * 16 + (k & 1) * 8 + g;
            atomicAdd(&g_rsum[br * 128 + r], v);
        }
    }
}

// ---------------------------------------------------------------------------
// Fused lse + finish: 64 blocks reduce lse -> g_lse; the last block gathers
// g_lse + g_pos + g_sup*, writes the output, and resets g_done for replay.
__global__ void lse_kernel(float* __restrict__ out) {
    const int tid = threadIdx.x;
    const int lane = tid & 31, wib = tid >> 5;
    int i = blockIdx.x * blockDim.x + tid;
    float lse = 10.f + __logf(g_rsum[i]);
    #pragma unroll
    for (int o = 16; o; o >>= 1) lse += __shfl_xor_sync(0xffffffffu, lse, o);
    __shared__ float sh[8];
    __shared__ bool last;
    if (lane == 0) sh[wib] = lse;
    __syncthreads();
    if (tid == 0) {
        float t = 0.f;
        for (int k = 0; k < 8; k++) t += sh[k];
        g_lse[blockIdx.x] = t;
        __threadfence();
        last = (atomicAdd(&g_done, 1) == 63);
    }
    __syncthreads();
    if (last) {
        // cooperative gather of all partials
        float p = 0.f, l = 0.f, s0 = 0.f, s1 = 0.f, s2 = 0.f;
        #pragma unroll
        for (int k = 0; k < 4; k++) p += g_pos[tid + k * 256];
        if (tid < 64) l = g_lse[tid];
        if (tid < 32) { s0 = g_sup0[tid]; s1 = g_sup1[tid]; s2 = g_sup2[tid]; }
        #pragma unroll
        for (int o = 16; o; o >>= 1) {
            p  += __shfl_xor_sync(0xffffffffu, p,  o);
            l  += __shfl_xor_sync(0xffffffffu, l,  o);
            s0 += __shfl_xor_sync(0xffffffffu, s0, o);
            s1 += __shfl_xor_sync(0xffffffffu, s1, o);
            s2 += __shfl_xor_sync(0xffffffffu, s2, o);
        }
        __shared__ float sh2[5][8];
        if (lane == 0) {
            sh2[0][wib] = p; sh2[1][wib] = l;
            sh2[2][wib] = s0; sh2[3][wib] = s1; sh2[4][wib] = s2;
        }
        __syncthreads();
        if (tid == 0) {
            float tp = 0.f, tl = 0.f, t0 = 0.f, t1 = 0.f, t2 = 0.f;
            for (int k = 0; k < 8; k++) {
                tp += sh2[0][k]; tl += sh2[1][k];
                t0 += sh2[2][k]; t1 += sh2[3][k]; t2 += sh2[4][k];
            }
            const float inv = 1.f / 8192.f;
            float sup = t0 * inv + 0.5f * t1 * inv + 0.3f * t2 * inv;
            // sum_i sim_pos = 2 * posdotsum / 0.1 = 20 * posdotsum
            float ssl = (tl - 20.f * tp) * (1.f / 16384.f);
            out[0] = sup + 0.1f * ssl;
            g_done = 0;   // reset for next graph replay
        }
    }
}

// ---------------------------------------------------------------------------
extern "C" void kernel_launch(void* const* d_in, const int* in_sizes, int n_in,
                              void* d_out, int out_size) {
    const float* pp = (const float*)d_in[0];
    const float* pt = (const float*)d_in[1];
    const float* cp = (const float*)d_in[2];
    const float* ct = (const float*)d_in[3];
    const float* xp = (const float*)d_in[4];
    const float* xt = (const float*)d_in[5];
    const float* z1 = (const float*)d_in[6];
    const float* z2 = (const float*)d_in[7];
    float* out = (float*)d_out;

    cudaFuncSetAttribute(ntxent_kernel, cudaFuncAttributeMaxDynamicSharedMemorySize,
                         SMEM_BYTES);

    prep_kernel<<<1024, 256>>>(z1, z2, pp, pt, cp, ct, xp, xt);
    ntxent_kernel<<<128, 256, SMEM_BYTES>>>();
    lse_kernel<<<64, 256>>>(out);
}